// round 10
// baseline (speedup 1.0000x reference)
#include <cuda_runtime.h>
#include <cstdint>
#include <math.h>

#define BB 2
#define SS 2048
#define DD 2048
#define HH 16
#define DH 128

// fp32 scratch for Q,K,V in (b,h,s,dh) layout (values pre-rounded to tf32)
__device__ float g_q[BB*HH*SS*DH];
__device__ float g_k[BB*HH*SS*DH];
__device__ float g_v[BB*HH*SS*DH];
// tf32-rounded copies of inputs (so proj can cp.async without a cvt step)
__device__ float g_xr[BB*SS*DD];
__device__ float g_wr[3][DD*DD];

__device__ __forceinline__ uint32_t f2tf(float f) {
    uint32_t r;
    asm("cvt.rna.tf32.f32 %0, %1;" : "=r"(r) : "f"(f));
    return r;
}

__device__ __forceinline__ void mma8(float* c, const uint32_t* a, uint32_t b0, uint32_t b1) {
    asm volatile(
        "mma.sync.aligned.m16n8k8.row.col.f32.tf32.tf32.f32 "
        "{%0,%1,%2,%3}, {%4,%5,%6,%7}, {%8,%9}, {%0,%1,%2,%3};\n"
        : "+f"(c[0]), "+f"(c[1]), "+f"(c[2]), "+f"(c[3])
        : "r"(a[0]), "r"(a[1]), "r"(a[2]), "r"(a[3]), "r"(b0), "r"(b1));
}

__device__ __forceinline__ void cp16(uint32_t s, const float* g) {
    asm volatile("cp.async.cg.shared.global [%0], [%1], 16;\n" :: "r"(s), "l"(g));
}
#define CP_COMMIT() asm volatile("cp.async.commit_group;\n" ::: "memory")

// ===================== Pre-pass: rna-round inputs to tf32 =====================
__global__ void round_kernel(const float* __restrict__ src, int sel, int n4) {
    float* dst = (sel == 0) ? g_xr : g_wr[sel - 1];
    int i = blockIdx.x * blockDim.x + threadIdx.x;
    int stride = gridDim.x * blockDim.x;
    for (; i < n4; i += stride) {
        float4 v = ((const float4*)src)[i];
        uint4 r;
        r.x = f2tf(v.x); r.y = f2tf(v.y); r.z = f2tf(v.z); r.w = f2tf(v.w);
        ((uint4*)dst)[i] = r;
    }
}

// ===================== Projection GEMM (+ fused RoPE) =====================
// C[token, o] = sum_k xr[token,k] * wr[o,k]
// CTA tile: M=256, N=128, BK=32.  Warp tile 64x64 (8 warps: 4 m x 2 n).
// 3-stage cp.async pipeline, one wait+barrier per K-iter.
// grid: (2048/128=16, 4096/256=16, 3[q,k,v]); 256 threads; 162KB smem (occ 1).
#define PJ_STR 36
#define PJ_A_WORDS (256 * PJ_STR)                 // 9216
#define PJ_B_WORDS (128 * PJ_STR)                 // 4608
#define PJ_STAGE_WORDS (PJ_A_WORDS + PJ_B_WORDS)  // 13824
#define PJ_SMEM_BYTES (3 * PJ_STAGE_WORDS * 4)    // 165888

__device__ __forceinline__ void pj_issue(uint32_t stage_addr, const float* abase,
                                         const float* bbase, int k0, int tid) {
    // A tile: 256 rows x 32 cols -> 2048 16B-chunks, 8 per thread
#pragma unroll
    for (int i = 0; i < 8; i++) {
        int c = tid + 256 * i;
        int row = c >> 3, ch = c & 7;
        cp16(stage_addr + (row * PJ_STR + ch * 4) * 4, abase + row * DD + k0 + ch * 4);
    }
    // B tile: 128 rows x 32 cols -> 1024 chunks, 4 per thread
#pragma unroll
    for (int i = 0; i < 4; i++) {
        int c = tid + 256 * i;
        int row = c >> 3, ch = c & 7;
        cp16(stage_addr + (PJ_A_WORDS + row * PJ_STR + ch * 4) * 4,
             bbase + row * DD + k0 + ch * 4);
    }
    CP_COMMIT();
}

__global__ __launch_bounds__(256, 1) void proj_kernel(
    const float* __restrict__ rcos, const float* __restrict__ rsin)
{
    extern __shared__ uint32_t psm[];
    const uint32_t smem_base = (uint32_t)__cvta_generic_to_shared(psm);

    const int z = blockIdx.z;
    const float* abase = g_xr + (size_t)blockIdx.y * 256 * DD;
    const float* bbase = g_wr[z] + (size_t)blockIdx.x * 128 * DD;
    float* outp = (z == 0) ? g_q : (z == 1) ? g_k : g_v;
    const bool rope = (z < 2);
    const int m0 = blockIdx.y * 256, n0 = blockIdx.x * 128;

    const int tid = threadIdx.x, lane = tid & 31, wid = tid >> 5;
    const int wm = wid >> 1, wn = wid & 1;
    const int g = lane >> 2, qd = lane & 3;

    float acc[4][8][4];
#pragma unroll
    for (int mi = 0; mi < 4; mi++)
#pragma unroll
        for (int nf = 0; nf < 8; nf++)
#pragma unroll
            for (int e = 0; e < 4; e++) acc[mi][nf][e] = 0.f;

    // prologue: stages 0,1 in flight
    pj_issue(smem_base + 0 * PJ_STAGE_WORDS * 4, abase, bbase, 0, tid);
    pj_issue(smem_base + 1 * PJ_STAGE_WORDS * 4, abase, bbase, 32, tid);

    for (int it = 0; it < 64; it++) {
        if (it < 63) {
            asm volatile("cp.async.wait_group 1;\n" ::: "memory");
        } else {
            asm volatile("cp.async.wait_group 0;\n" ::: "memory");
        }
        __syncthreads();   // all warps: group `it` data visible; compute(it-1) done

        // issue stage it+2 (overwrites stage (it-1)%3, finished by all warps)
        if (it + 2 < 64)
            pj_issue(smem_base + ((it + 2) % 3) * PJ_STAGE_WORDS * 4,
                     abase, bbase, (it + 2) * 32, tid);

        const uint32_t* Ac = psm + (it % 3) * PJ_STAGE_WORDS;
        const uint32_t* Bc = Ac + PJ_A_WORDS;
#pragma unroll
        for (int ks = 0; ks < 4; ks++) {
            const int kk = ks * 8;
            uint32_t a[4][4];
#pragma unroll
            for (int mi = 0; mi < 4; mi++) {
                int row = wm * 64 + mi * 16 + g;
                a[mi][0] = Ac[row * PJ_STR + kk + qd];
                a[mi][1] = Ac[(row + 8) * PJ_STR + kk + qd];
                a[mi][2] = Ac[row * PJ_STR + kk + qd + 4];
                a[mi][3] = Ac[(row + 8) * PJ_STR + kk + qd + 4];
            }
#pragma unroll
            for (int nf = 0; nf < 8; nf++) {
                int col = wn * 64 + nf * 8 + g;
                uint32_t b0 = Bc[col * PJ_STR + kk + qd];
                uint32_t b1 = Bc[col * PJ_STR + kk + qd + 4];
#pragma unroll
                for (int mi = 0; mi < 4; mi++)
                    mma8(acc[mi][nf], a[mi], b0, b1);
            }
        }
    }

    // Epilogue: RoPE (fp32, register-local pairs), round to tf32, store (b,h,s,dh)
#pragma unroll
    for (int mi = 0; mi < 4; mi++) {
#pragma unroll
        for (int hh = 0; hh < 2; hh++) {
            int row = m0 + wm * 64 + mi * 16 + g + hh * 8;   // token id
            int b = row >> 11;          // /S
            int s = row & (SS - 1);
#pragma unroll
            for (int nf = 0; nf < 8; nf++) {
                int col = n0 + wn * 64 + nf * 8 + qd * 2;    // even
                int h = col >> 7, dh = col & 127;
                float v0 = acc[mi][nf][hh * 2 + 0];
                float v1 = acc[mi][nf][hh * 2 + 1];
                if (rope) {
                    float c = rcos[s * DH + dh];
                    float sn = rsin[s * DH + dh];
                    float r0 = v0 * c - v1 * sn;
                    float r1 = v1 * c + v0 * sn;
                    v0 = r0; v1 = r1;
                }
                v0 = __uint_as_float(f2tf(v0));
                v1 = __uint_as_float(f2tf(v1));
                float2* dst = (float2*)(outp + (((size_t)b * HH + h) * SS + s) * DH + dh);
                *dst = make_float2(v0, v1);
            }
        }
    }
}

// ===================== Flash attention + final Dh softmax =====================
// (exact Round-2 kernel — measured 375us; do not touch)
#define QS_STR 132
#define KS_STR 132
#define VS_STR 136
#define PS_STR 68
#define OFF_Q 0
#define OFF_K (128 * QS_STR)
#define OFF_V (OFF_K + 64 * KS_STR)
#define OFF_P (OFF_V + 64 * VS_STR)
#define SMEM_FLOATS (OFF_P + 128 * PS_STR)
#define SMEM_BYTES (SMEM_FLOATS * 4)

__global__ __launch_bounds__(256, 1) void flash_kernel(float* __restrict__ out)
{
    extern __shared__ uint32_t sm[];
    uint32_t* Qs = sm + OFF_Q;
    uint32_t* Ks = sm + OFF_K;
    uint32_t* Vs = sm + OFF_V;
    uint32_t* Ps = sm + OFF_P;

    const int tid = threadIdx.x, lane = tid & 31, wid = tid >> 5;
    const int bh = blockIdx.y;
    const int qt = gridDim.x - 1 - blockIdx.x;   // big tiles launch first
    const int q0 = qt * 128;
    const int g = lane >> 2, qd = lane & 3;
    const int rw0 = q0 + wid * 16;
    const float e2 = (float)(1.4426950408889634 / 11.313708498984761); // log2(e)/sqrt(128)

    // stage Q tile (128 x 128)
#pragma unroll
    for (int i = 0; i < 16; i++) {
        int idx = tid + 256 * i;
        int r = idx >> 5;
        int c4 = (idx & 31) * 4;
        float4 v = *(const float4*)(g_q + (bh * SS + q0 + r) * DH + c4);
        uint32_t* dst = Qs + r * QS_STR + c4;
        dst[0] = f2tf(v.x); dst[1] = f2tf(v.y); dst[2] = f2tf(v.z); dst[3] = f2tf(v.w);
    }

    float oacc[16][4];
#pragma unroll
    for (int nf = 0; nf < 16; nf++)
#pragma unroll
        for (int e = 0; e < 4; e++) oacc[nf][e] = 0.f;
    float m2[2] = {-INFINITY, -INFINITY};
    float lsum[2] = {0.f, 0.f};

    const int ntiles = qt * 2 + 2;
    for (int t = 0; t < ntiles; t++) {
        const int k0g = t * 64;
        __syncthreads();
        // stage K,V tiles (64 x 128)
#pragma unroll
        for (int i = 0; i < 8; i++) {
            int idx = tid + 256 * i;
            int r = idx >> 5;
            int c4 = (idx & 31) * 4;
            float4 vk = *(const float4*)(g_k + (bh * SS + k0g + r) * DH + c4);
            uint32_t* dk = Ks + r * KS_STR + c4;
            dk[0] = f2tf(vk.x); dk[1] = f2tf(vk.y); dk[2] = f2tf(vk.z); dk[3] = f2tf(vk.w);
            float4 vv = *(const float4*)(g_v + (bh * SS + k0g + r) * DH + c4);
            uint32_t* dv = Vs + r * VS_STR + c4;
            dv[0] = f2tf(vv.x); dv[1] = f2tf(vv.y); dv[2] = f2tf(vv.z); dv[3] = f2tf(vv.w);
        }
        __syncthreads();

        const bool active = (k0g <= rw0 + 15);
        if (active) {
            float sacc[8][4];
#pragma unroll
            for (int nf = 0; nf < 8; nf++)
#pragma unroll
                for (int e = 0; e < 4; e++) sacc[nf][e] = 0.f;

            // S = Q K^T (k-dim = Dh = 128 -> 16 ksteps)
#pragma unroll
            for (int kd = 0; kd < 16; kd++) {
                const int kk = kd * 8;
                uint32_t a[4];
                int qrow = wid * 16 + g;
                a[0] = Qs[qrow * QS_STR + kk + qd];
                a[1] = Qs[(qrow + 8) * QS_STR + kk + qd];
                a[2] = Qs[qrow * QS_STR + kk + qd + 4];
                a[3] = Qs[(qrow + 8) * QS_STR + kk + qd + 4];
#pragma unroll
                for (int nf = 0; nf < 8; nf++) {
                    int krow = nf * 8 + g;
                    uint32_t b0 = Ks[krow * KS_STR + kk + qd];
                    uint32_t b1 = Ks[krow * KS_STR + kk + qd + 4];
                    mma8(sacc[nf], a, b0, b1);
                }
            }

            const bool needmask = (k0g + 63 > rw0);
#pragma unroll
            for (int hh = 0; hh < 2; hh++) {
                int rg = rw0 + g + hh * 8;
                float rmax = -INFINITY;
#pragma unroll
                for (int nf = 0; nf < 8; nf++) {
#pragma unroll
                    for (int e = 0; e < 2; e++) {
                        int col = k0g + nf * 8 + qd * 2 + e;
                        float sv = sacc[nf][hh * 2 + e] * e2;
                        if (needmask && col > rg) sv = -1e30f;
                        sacc[nf][hh * 2 + e] = sv;
                        rmax = fmaxf(rmax, sv);
                    }
                }
                rmax = fmaxf(rmax, __shfl_xor_sync(0xffffffffu, rmax, 1));
                rmax = fmaxf(rmax, __shfl_xor_sync(0xffffffffu, rmax, 2));
                float mnew = fmaxf(m2[hh], rmax);
                float corr = exp2f(m2[hh] - mnew);
                m2[hh] = mnew;
                float psum = 0.f;
#pragma unroll
                for (int nf = 0; nf < 8; nf++) {
#pragma unroll
                    for (int e = 0; e < 2; e++) {
                        float p = exp2f(sacc[nf][hh * 2 + e] - mnew);
                        psum += p;
                        sacc[nf][hh * 2 + e] = __uint_as_float(f2tf(p));
                    }
                }
                psum += __shfl_xor_sync(0xffffffffu, psum, 1);
                psum += __shfl_xor_sync(0xffffffffu, psum, 2);
                lsum[hh] = lsum[hh] * corr + psum;
#pragma unroll
                for (int nf = 0; nf < 16; nf++) {
                    oacc[nf][hh * 2 + 0] *= corr;
                    oacc[nf][hh * 2 + 1] *= corr;
                }
                int prow = wid * 16 + g + hh * 8;
#pragma unroll
                for (int nf = 0; nf < 8; nf++) {
                    Ps[prow * PS_STR + nf * 8 + qd * 2 + 0] = __float_as_uint(sacc[nf][hh * 2 + 0]);
                    Ps[prow * PS_STR + nf * 8 + qd * 2 + 1] = __float_as_uint(sacc[nf][hh * 2 + 1]);
                }
            }
            __syncwarp();

            // O += P V
#pragma unroll
            for (int j = 0; j < 8; j++) {
                uint32_t a[4];
                int prow = wid * 16 + g;
                a[0] = Ps[prow * PS_STR + j * 8 + qd];
                a[1] = Ps[(prow + 8) * PS_STR + j * 8 + qd];
                a[2] = Ps[prow * PS_STR + j * 8 + qd + 4];
                a[3] = Ps[(prow + 8) * PS_STR + j * 8 + qd + 4];
#pragma unroll
                for (int nf = 0; nf < 16; nf++) {
                    uint32_t b0 = Vs[(j * 8 + qd) * VS_STR + nf * 8 + g];
                    uint32_t b1 = Vs[(j * 8 + qd + 4) * VS_STR + nf * 8 + g];
                    mma8(oacc[nf], a, b0, b1);
                }
            }
        }
    }

    // Epilogue: O /= l, then softmax over Dh=128, write fp32
    const int b = bh >> 4, h = bh & 15;
#pragma unroll
    for (int hh = 0; hh < 2; hh++) {
        int srow = rw0 + g + hh * 8;
        float inv = 1.0f / lsum[hh];
        float vals[32];
        float mx = -INFINITY;
#pragma unroll
        for (int nf = 0; nf < 16; nf++) {
            vals[nf * 2 + 0] = oacc[nf][hh * 2 + 0] * inv;
            vals[nf * 2 + 1] = oacc[nf][hh * 2 + 1] * inv;
            mx = fmaxf(mx, fmaxf(vals[nf * 2], vals[nf * 2 + 1]));
        }
        mx = fmaxf(mx, __shfl_xor_sync(0xffffffffu, mx, 1));
        mx = fmaxf(mx, __shfl_xor_sync(0xffffffffu, mx, 2));
        float ssum = 0.f;
#pragma unroll
        for (int i2 = 0; i2 < 32; i2++) {
            vals[i2] = expf(vals[i2] - mx);
            ssum += vals[i2];
        }
        ssum += __shfl_xor_sync(0xffffffffu, ssum, 1);
        ssum += __shfl_xor_sync(0xffffffffu, ssum, 2);
        float rinv = 1.0f / ssum;
#pragma unroll
        for (int nf = 0; nf < 16; nf++) {
            int col = h * 128 + nf * 8 + qd * 2;
            float2* dst = (float2*)(out + (b * SS + srow) * DD + col);
            *dst = make_float2(vals[nf * 2] * rinv, vals[nf * 2 + 1] * rinv);
        }
    }
}

extern "C" void kernel_launch(void* const* d_in, const int* in_sizes, int n_in,
                              void* d_out, int out_size)
{
    const float* x    = (const float*)d_in[0];
    const float* wq   = (const float*)d_in[1];
    const float* wk   = (const float*)d_in[2];
    const float* wv   = (const float*)d_in[3];
    const float* rcos = (const float*)d_in[4];
    const float* rsin = (const float*)d_in[5];
    float* out = (float*)d_out;

    static bool attr_set = false;
    if (!attr_set) {
        cudaFuncSetAttribute(flash_kernel, cudaFuncAttributeMaxDynamicSharedMemorySize, SMEM_BYTES);
        cudaFuncSetAttribute(proj_kernel,  cudaFuncAttributeMaxDynamicSharedMemorySize, PJ_SMEM_BYTES);
        attr_set = true;
    }

    const int nblk = 1184;
    round_kernel<<<nblk, 256>>>(x,  0, (BB * SS * DD) / 4);
    round_kernel<<<nblk, 256>>>(wq, 1, (DD * DD) / 4);
    round_kernel<<<nblk, 256>>>(wk, 2, (DD * DD) / 4);
    round_kernel<<<nblk, 256>>>(wv, 3, (DD * DD) / 4);

    proj_kernel<<<dim3(16, 16, 3), 256, PJ_SMEM_BYTES>>>(rcos, rsin);
    flash_kernel<<<dim3(16, BB * HH), 256, SMEM_BYTES>>>(out);
}

// round 13
// speedup vs baseline: 1.6192x; 1.6192x over previous
#include <cuda_runtime.h>
#include <cstdint>
#include <math.h>

#define BB 2
#define SS 2048
#define DD 2048
#define HH 16
#define DH 128

// fp32 scratch for Q,K,V in (b,h,s,dh) layout (values pre-rounded to tf32)
__device__ float g_q[BB*HH*SS*DH];
__device__ float g_k[BB*HH*SS*DH];
__device__ float g_v[BB*HH*SS*DH];
// tf32-rounded copies of inputs (so proj can cp.async without a cvt step)
__device__ float g_xr[BB*SS*DD];
__device__ float g_wr[3][DD*DD];

__device__ __forceinline__ uint32_t f2tf(float f) {
    uint32_t r;
    asm("cvt.rna.tf32.f32 %0, %1;" : "=r"(r) : "f"(f));
    return r;
}

__device__ __forceinline__ void mma8(float* c, const uint32_t* a, uint32_t b0, uint32_t b1) {
    asm volatile(
        "mma.sync.aligned.m16n8k8.row.col.f32.tf32.tf32.f32 "
        "{%0,%1,%2,%3}, {%4,%5,%6,%7}, {%8,%9}, {%0,%1,%2,%3};\n"
        : "+f"(c[0]), "+f"(c[1]), "+f"(c[2]), "+f"(c[3])
        : "r"(a[0]), "r"(a[1]), "r"(a[2]), "r"(a[3]), "r"(b0), "r"(b1));
}

__device__ __forceinline__ void cp16(uint32_t s, const float* g) {
    asm volatile("cp.async.cg.shared.global [%0], [%1], 16;\n" :: "r"(s), "l"(g));
}
#define CP_COMMIT() asm volatile("cp.async.commit_group;\n" ::: "memory")

// ===================== Pre-pass: rna-round inputs to tf32 =====================
__global__ void round_kernel(const float* __restrict__ src, int sel, int n4) {
    float* dst = (sel == 0) ? g_xr : g_wr[sel - 1];
    int i = blockIdx.x * blockDim.x + threadIdx.x;
    int stride = gridDim.x * blockDim.x;
    for (; i < n4; i += stride) {
        float4 v = ((const float4*)src)[i];
        uint4 r;
        r.x = f2tf(v.x); r.y = f2tf(v.y); r.z = f2tf(v.z); r.w = f2tf(v.w);
        ((uint4*)dst)[i] = r;
    }
}

// ===================== Projection GEMM (+ fused RoPE) =====================
// EXACT Round-6 kernel (measured: proj ~614us within 1012us total). Do not touch.
// C[token, o] = sum_k xr[token,k] * wr[o,k]; block tile 128x128, BK=32, tf32 mma.
// 3-stage cp.async pipeline, one __syncthreads per K-iter.
#define PJ_STR 36
#define PJ_STAGE (128 * PJ_STR)
#define PJ_SMEM_BYTES (2 * 3 * PJ_STAGE * 4)

__global__ __launch_bounds__(256, 2) void proj_kernel(
    const float* __restrict__ rcos, const float* __restrict__ rsin)
{
    extern __shared__ uint32_t psm[];
    const uint32_t smem_base = (uint32_t)__cvta_generic_to_shared(psm);

    const int z = blockIdx.z;
    const float* xr = g_xr;
    const float* wr = g_wr[z];
    float* outp = (z == 0) ? g_q : (z == 1) ? g_k : g_v;
    const bool rope = (z < 2);

    const int tid = threadIdx.x, lane = tid & 31, wid = tid >> 5;
    const int wm = wid >> 1, wn = wid & 1;
    const int m0 = blockIdx.y * 128, n0 = blockIdx.x * 128;
    const int g = lane >> 2, qd = lane & 3;

    float acc[2][8][4];
#pragma unroll
    for (int mi = 0; mi < 2; mi++)
#pragma unroll
        for (int nf = 0; nf < 8; nf++)
#pragma unroll
            for (int e = 0; e < 4; e++) acc[mi][nf][e] = 0.f;

    const int lr = tid >> 3;          // 0..31
    const int lc = (tid & 7) * 4;     // 0..28
    const float* asrc = xr + (m0 + lr) * DD + lc;
    const float* bsrc = wr + (n0 + lr) * DD + lc;
    const uint32_t adst = smem_base + (lr * PJ_STR + lc) * 4;
    const uint32_t bdst = smem_base + (3 * PJ_STAGE + lr * PJ_STR + lc) * 4;

#define PJ_ISSUE(kt, st) do { \
        const float* xa_ = asrc + (kt) * 32; \
        const float* wb_ = bsrc + (kt) * 32; \
        uint32_t ad_ = adst + (st) * (PJ_STAGE * 4); \
        uint32_t bd_ = bdst + (st) * (PJ_STAGE * 4); \
        _Pragma("unroll") \
        for (int p = 0; p < 4; p++) { \
            cp16(ad_ + p * (32 * PJ_STR * 4), xa_ + p * (32 * DD)); \
            cp16(bd_ + p * (32 * PJ_STR * 4), wb_ + p * (32 * DD)); \
        } \
        CP_COMMIT(); \
    } while (0)

    PJ_ISSUE(0, 0);
    PJ_ISSUE(1, 1);

    for (int it = 0; it < 64; it++) {
        if (it < 63) {
            asm volatile("cp.async.wait_group 1;\n" ::: "memory");
        } else {
            asm volatile("cp.async.wait_group 0;\n" ::: "memory");
        }
        __syncthreads();

        const int st = it % 3;
        const uint32_t* Ac = psm + st * PJ_STAGE;
        const uint32_t* Bc = psm + 3 * PJ_STAGE + st * PJ_STAGE;
#pragma unroll
        for (int ks = 0; ks < 4; ks++) {
            const int kk = ks * 8;
            uint32_t a[2][4];
#pragma unroll
            for (int mi = 0; mi < 2; mi++) {
                int row = wm * 32 + mi * 16 + g;
                a[mi][0] = Ac[row * PJ_STR + kk + qd];
                a[mi][1] = Ac[(row + 8) * PJ_STR + kk + qd];
                a[mi][2] = Ac[row * PJ_STR + kk + qd + 4];
                a[mi][3] = Ac[(row + 8) * PJ_STR + kk + qd + 4];
            }
#pragma unroll
            for (int nf = 0; nf < 8; nf++) {
                int col = wn * 64 + nf * 8 + g;
                uint32_t b0 = Bc[col * PJ_STR + kk + qd];
                uint32_t b1 = Bc[col * PJ_STR + kk + qd + 4];
                mma8(acc[0][nf], a[0], b0, b1);
                mma8(acc[1][nf], a[1], b0, b1);
            }
        }

        if (it + 2 < 64) PJ_ISSUE(it + 2, (it + 2) % 3);
    }
#undef PJ_ISSUE

#pragma unroll
    for (int mi = 0; mi < 2; mi++) {
#pragma unroll
        for (int hh = 0; hh < 2; hh++) {
            int row = m0 + wm * 32 + mi * 16 + g + hh * 8;   // token id
            int b = row >> 11;
            int s = row & (SS - 1);
#pragma unroll
            for (int nf = 0; nf < 8; nf++) {
                int col = n0 + wn * 64 + nf * 8 + qd * 2;
                int h = col >> 7, dh = col & 127;
                float v0 = acc[mi][nf][hh * 2 + 0];
                float v1 = acc[mi][nf][hh * 2 + 1];
                if (rope) {
                    float c = rcos[s * DH + dh];
                    float sn = rsin[s * DH + dh];
                    float r0 = v0 * c - v1 * sn;
                    float r1 = v1 * c + v0 * sn;
                    v0 = r0; v1 = r1;
                }
                v0 = __uint_as_float(f2tf(v0));
                v1 = __uint_as_float(f2tf(v1));
                float2* dst = (float2*)(outp + (((size_t)b * HH + h) * SS + s) * DH + dh);
                *dst = make_float2(v0, v1);
            }
        }
    }
}

// ===================== Flash attention + final Dh softmax =====================
// 128 threads (4 warps), q-tile 64, swizzled smem (no padding) -> 112KB/CTA
// -> 2 CTAs/SM. Swizzles: Q/K/P col^((row&7)<<2); V col^((row&7)<<3).
#define OFF_Q 0
#define OFF_K 8192
#define OFF_V 16384
#define OFF_P 24576
#define FL_SMEM_BYTES ((24576 + 4096) * 4)   // 114688 B = 112KB

__global__ __launch_bounds__(128, 2) void flash_kernel(float* __restrict__ out)
{
    extern __shared__ uint32_t sm[];
    uint32_t* Qs = sm + OFF_Q;
    uint32_t* Ks = sm + OFF_K;
    uint32_t* Vs = sm + OFF_V;
    uint32_t* Ps = sm + OFF_P;

    const int tid = threadIdx.x, lane = tid & 31, wid = tid >> 5;  // wid 0..3
    const int bh = blockIdx.y;
    const int qt = gridDim.x - 1 - blockIdx.x;   // big tiles launch first
    const int q0 = qt * 64;
    const int g = lane >> 2, qd = lane & 3;
    const int rw0 = q0 + wid * 16;
    const float e2 = (float)(1.4426950408889634 / 11.313708498984761); // log2(e)/sqrt(128)

    // stage Q tile (64 x 128), swizzle <<2
#pragma unroll
    for (int i = 0; i < 16; i++) {
        int idx = tid + 128 * i;
        int r = idx >> 5;
        int c4 = (idx & 31) * 4;
        float4 v = *(const float4*)(g_q + ((size_t)bh * SS + q0 + r) * DH + c4);
        uint32_t* dst = Qs + r * 128 + (c4 ^ ((r & 7) << 2));
        dst[0] = f2tf(v.x); dst[1] = f2tf(v.y); dst[2] = f2tf(v.z); dst[3] = f2tf(v.w);
    }

    float oacc[16][4];
#pragma unroll
    for (int nf = 0; nf < 16; nf++)
#pragma unroll
        for (int e = 0; e < 4; e++) oacc[nf][e] = 0.f;
    float m2[2] = {-INFINITY, -INFINITY};
    float lsum[2] = {0.f, 0.f};

    const int ntiles = qt + 1;
    for (int t = 0; t < ntiles; t++) {
        const int k0g = t * 64;
        __syncthreads();
        // stage K (swizzle <<2) and V (swizzle <<3) tiles, 64 x 128 each
#pragma unroll
        for (int i = 0; i < 16; i++) {
            int idx = tid + 128 * i;
            int r = idx >> 5;
            int c4 = (idx & 31) * 4;
            float4 vk = *(const float4*)(g_k + ((size_t)bh * SS + k0g + r) * DH + c4);
            uint32_t* dk = Ks + r * 128 + (c4 ^ ((r & 7) << 2));
            dk[0] = f2tf(vk.x); dk[1] = f2tf(vk.y); dk[2] = f2tf(vk.z); dk[3] = f2tf(vk.w);
            float4 vv = *(const float4*)(g_v + ((size_t)bh * SS + k0g + r) * DH + c4);
            uint32_t* dv = Vs + r * 128 + (c4 ^ ((r & 7) << 3));
            dv[0] = f2tf(vv.x); dv[1] = f2tf(vv.y); dv[2] = f2tf(vv.z); dv[3] = f2tf(vv.w);
        }
        __syncthreads();

        // all warps active on every staged tile (k0g <= q0 <= rw0+15)
        float sacc[8][4];
#pragma unroll
        for (int nf = 0; nf < 8; nf++)
#pragma unroll
            for (int e = 0; e < 4; e++) sacc[nf][e] = 0.f;

        // S = Q K^T (k-dim = Dh = 128 -> 16 ksteps)
        const int qrow = wid * 16 + g;
        const int xsw = g << 2;     // (row&7)<<2 for rows qrow, qrow+8, krow (all &7 == g)
#pragma unroll
        for (int kd = 0; kd < 16; kd++) {
            const int kk = kd * 8;
            uint32_t a[4];
            a[0] = Qs[qrow * 128 + ((kk + qd) ^ xsw)];
            a[1] = Qs[(qrow + 8) * 128 + ((kk + qd) ^ xsw)];
            a[2] = Qs[qrow * 128 + ((kk + qd + 4) ^ xsw)];
            a[3] = Qs[(qrow + 8) * 128 + ((kk + qd + 4) ^ xsw)];
#pragma unroll
            for (int nf = 0; nf < 8; nf++) {
                int krow = nf * 8 + g;
                uint32_t b0 = Ks[krow * 128 + ((kk + qd) ^ xsw)];
                uint32_t b1 = Ks[krow * 128 + ((kk + qd + 4) ^ xsw)];
                mma8(sacc[nf], a, b0, b1);
            }
        }

        const bool needmask = (k0g + 63 > rw0);
        // online softmax per row-half; scale folded into log2 domain
#pragma unroll
        for (int hh = 0; hh < 2; hh++) {
            int rg = rw0 + g + hh * 8;
            float rmax = -INFINITY;
#pragma unroll
            for (int nf = 0; nf < 8; nf++) {
#pragma unroll
                for (int e = 0; e < 2; e++) {
                    int col = k0g + nf * 8 + qd * 2 + e;
                    float sv = sacc[nf][hh * 2 + e] * e2;
                    if (needmask && col > rg) sv = -1e30f;
                    sacc[nf][hh * 2 + e] = sv;
                    rmax = fmaxf(rmax, sv);
                }
            }
            rmax = fmaxf(rmax, __shfl_xor_sync(0xffffffffu, rmax, 1));
            rmax = fmaxf(rmax, __shfl_xor_sync(0xffffffffu, rmax, 2));
            float mnew = fmaxf(m2[hh], rmax);
            float corr = exp2f(m2[hh] - mnew);
            m2[hh] = mnew;
            float psum = 0.f;
#pragma unroll
            for (int nf = 0; nf < 8; nf++) {
#pragma unroll
                for (int e = 0; e < 2; e++) {
                    float p = exp2f(sacc[nf][hh * 2 + e] - mnew);
                    psum += p;
                    sacc[nf][hh * 2 + e] = __uint_as_float(f2tf(p));
                }
            }
            psum += __shfl_xor_sync(0xffffffffu, psum, 1);
            psum += __shfl_xor_sync(0xffffffffu, psum, 2);
            lsum[hh] = lsum[hh] * corr + psum;
#pragma unroll
            for (int nf = 0; nf < 16; nf++) {
                oacc[nf][hh * 2 + 0] *= corr;
                oacc[nf][hh * 2 + 1] *= corr;
            }
            // write P (tf32 bits): row prow (&7 == g), swizzle <<2, pairs stay adjacent
            int prow = wid * 16 + g + hh * 8;
#pragma unroll
            for (int nf = 0; nf < 8; nf++) {
                uint32_t* dp = Ps + prow * 64 + ((nf * 8 + qd * 2) ^ xsw);
                dp[0] = __float_as_uint(sacc[nf][hh * 2 + 0]);
                dp[1] = __float_as_uint(sacc[nf][hh * 2 + 1]);
            }
        }
        __syncwarp();

        // O += P V  (k-dim = kv = 64 -> 8 ksteps, n = Dh = 128 -> 16 n-frags)
#pragma unroll
        for (int j = 0; j < 8; j++) {
            uint32_t a[4];
            const int prow = wid * 16 + g;
            a[0] = Ps[prow * 64 + ((j * 8 + qd) ^ xsw)];
            a[1] = Ps[(prow + 8) * 64 + ((j * 8 + qd) ^ xsw)];
            a[2] = Ps[prow * 64 + ((j * 8 + qd + 4) ^ xsw)];
            a[3] = Ps[(prow + 8) * 64 + ((j * 8 + qd + 4) ^ xsw)];
            const int vsw0 = qd << 3;               // rows j*8+qd   : (row&7)<<3
            const int vsw1 = ((qd + 4) & 7) << 3;   // rows j*8+qd+4
#pragma unroll
            for (int nf = 0; nf < 16; nf++) {
                uint32_t b0 = Vs[(j * 8 + qd) * 128 + ((nf * 8 + g) ^ vsw0)];
                uint32_t b1 = Vs[(j * 8 + qd + 4) * 128 + ((nf * 8 + g) ^ vsw1)];
                mma8(oacc[nf], a, b0, b1);
            }
        }
    }

    // Epilogue: O /= l, then softmax over Dh=128 (quad holds a full row), write fp32
    const int b = bh >> 4, h = bh & 15;
#pragma unroll
    for (int hh = 0; hh < 2; hh++) {
        int srow = rw0 + g + hh * 8;
        float inv = 1.0f / lsum[hh];
        float vals[32];
        float mx = -INFINITY;
#pragma unroll
        for (int nf = 0; nf < 16; nf++) {
            vals[nf * 2 + 0] = oacc[nf][hh * 2 + 0] * inv;
            vals[nf * 2 + 1] = oacc[nf][hh * 2 + 1] * inv;
            mx = fmaxf(mx, fmaxf(vals[nf * 2], vals[nf * 2 + 1]));
        }
        mx = fmaxf(mx, __shfl_xor_sync(0xffffffffu, mx, 1));
        mx = fmaxf(mx, __shfl_xor_sync(0xffffffffu, mx, 2));
        float ssum = 0.f;
#pragma unroll
        for (int i2 = 0; i2 < 32; i2++) {
            vals[i2] = expf(vals[i2] - mx);
            ssum += vals[i2];
        }
        ssum += __shfl_xor_sync(0xffffffffu, ssum, 1);
        ssum += __shfl_xor_sync(0xffffffffu, ssum, 2);
        float rinv = 1.0f / ssum;
#pragma unroll
        for (int nf = 0; nf < 16; nf++) {
            int col = h * 128 + nf * 8 + qd * 2;
            float2* dst = (float2*)(out + ((size_t)b * SS + srow) * DD + col);
            *dst = make_float2(vals[nf * 2] * rinv, vals[nf * 2 + 1] * rinv);
        }
    }
}

extern "C" void kernel_launch(void* const* d_in, const int* in_sizes, int n_in,
                              void* d_out, int out_size)
{
    const float* x    = (const float*)d_in[0];
    const float* wq   = (const float*)d_in[1];
    const float* wk   = (const float*)d_in[2];
    const float* wv   = (const float*)d_in[3];
    const float* rcos = (const float*)d_in[4];
    const float* rsin = (const float*)d_in[5];
    float* out = (float*)d_out;

    static bool attr_set = false;
    if (!attr_set) {
        cudaFuncSetAttribute(flash_kernel, cudaFuncAttributeMaxDynamicSharedMemorySize, FL_SMEM_BYTES);
        cudaFuncSetAttribute(proj_kernel,  cudaFuncAttributeMaxDynamicSharedMemorySize, PJ_SMEM_BYTES);
        attr_set = true;
    }

    const int nblk = 1184;
    round_kernel<<<nblk, 256>>>(x,  0, (BB * SS * DD) / 4);
    round_kernel<<<nblk, 256>>>(wq, 1, (DD * DD) / 4);
    round_kernel<<<nblk, 256>>>(wk, 2, (DD * DD) / 4);
    round_kernel<<<nblk, 256>>>(wv, 3, (DD * DD) / 4);

    proj_kernel<<<dim3(16, 32, 3), 256, PJ_SMEM_BYTES>>>(rcos, rsin);
    flash_kernel<<<dim3(32, BB * HH), 128, FL_SMEM_BYTES>>>(out);
}

// round 15
// speedup vs baseline: 2.8854x; 1.7820x over previous
#include <cuda_runtime.h>
#include <cuda_fp16.h>
#include <cstdint>
#include <math.h>

#define BB 2
#define SS 2048
#define DD 2048
#define HH 16
#define DH 128

// fp16 scratch: Q,K in (b,h,s,dh); V TRANSPOSED in (b,h,dh,s)
__device__ __half g_q[BB*HH*SS*DH];
__device__ __half g_k[BB*HH*SS*DH];
__device__ __half g_v[BB*HH*SS*DH];
// fp16-rounded copies of inputs (so proj can cp.async without a cvt step)
__device__ __half g_xr[BB*SS*DD];
__device__ __half g_wr[3][DD*DD];

__device__ __forceinline__ void mma16(float* c, const uint32_t* a, uint32_t b0, uint32_t b1) {
    asm volatile(
        "mma.sync.aligned.m16n8k16.row.col.f32.f16.f16.f32 "
        "{%0,%1,%2,%3}, {%4,%5,%6,%7}, {%8,%9}, {%0,%1,%2,%3};\n"
        : "+f"(c[0]), "+f"(c[1]), "+f"(c[2]), "+f"(c[3])
        : "r"(a[0]), "r"(a[1]), "r"(a[2]), "r"(a[3]), "r"(b0), "r"(b1));
}

__device__ __forceinline__ void cp16(uint32_t s, const void* g) {
    asm volatile("cp.async.cg.shared.global [%0], [%1], 16;\n" :: "r"(s), "l"(g));
}
#define CP_COMMIT() asm volatile("cp.async.commit_group;\n" ::: "memory")

__device__ __forceinline__ uint32_t h2u(__half2 h) {
    return *(uint32_t*)&h;
}

// ===================== Pre-pass: round inputs to fp16 =====================
// sel: 0 -> x into g_xr, 1..3 -> wq/wk/wv into g_wr[sel-1]. n8 = elems/8.
__global__ void round_kernel(const float* __restrict__ src, int sel, int n8) {
    __half* dst = (sel == 0) ? g_xr : g_wr[sel - 1];
    int i = blockIdx.x * blockDim.x + threadIdx.x;
    int stride = gridDim.x * blockDim.x;
    for (; i < n8; i += stride) {
        float4 v0 = ((const float4*)src)[2 * i];
        float4 v1 = ((const float4*)src)[2 * i + 1];
        uint4 o;
        o.x = h2u(__floats2half2_rn(v0.x, v0.y));
        o.y = h2u(__floats2half2_rn(v0.z, v0.w));
        o.z = h2u(__floats2half2_rn(v1.x, v1.y));
        o.w = h2u(__floats2half2_rn(v1.z, v1.w));
        ((uint4*)dst)[i] = o;
    }
}

// ===================== Projection GEMM (+ fused RoPE), fp16 =====================
// C[token, o] = sum_k xr[token,k] * wr[o,k]; tile 128x128, BK=64 halves, m16n8k16.
// R6-proven 3-stage cp.async skeleton (wait/sync/compute/issue), occ 2.
// grid: (16, 32, 3[q,k,v]); smem 2 mats * 3 stages * 128*36 words = 110592 B.
#define PJ_STR 36
#define PJ_STAGE (128 * PJ_STR)
#define PJ_SMEM_BYTES (2 * 3 * PJ_STAGE * 4)

__device__ __forceinline__ void pj_issue(uint32_t sbA, uint32_t sbB,
                                         const __half* abase, const __half* bbase,
                                         int k0, int tid) {
    // 128 rows x 8 chunks (of 8 halves = 16B) per matrix = 1024 chunks; 4/thread
#pragma unroll
    for (int i = 0; i < 4; i++) {
        int idx = tid + 256 * i;
        int row = idx >> 3, c = idx & 7;
        cp16(sbA + (row * PJ_STR + c * 4) * 4, abase + row * DD + k0 + c * 8);
        cp16(sbB + (row * PJ_STR + c * 4) * 4, bbase + row * DD + k0 + c * 8);
    }
    CP_COMMIT();
}

__global__ __launch_bounds__(256, 2) void proj_kernel(
    const float* __restrict__ rcos, const float* __restrict__ rsin)
{
    extern __shared__ uint32_t psm[];
    const uint32_t smem_base = (uint32_t)__cvta_generic_to_shared(psm);

    const int z = blockIdx.z;
    const __half* abase = g_xr + (size_t)blockIdx.y * 128 * DD;
    const __half* bbase = g_wr[z] + (size_t)blockIdx.x * 128 * DD;
    __half* outp = (z == 0) ? g_q : (z == 1) ? g_k : g_v;
    const int m0 = blockIdx.y * 128, n0 = blockIdx.x * 128;

    const int tid = threadIdx.x, lane = tid & 31, wid = tid >> 5;
    const int wm = wid >> 1, wn = wid & 1;
    const int g = lane >> 2, qd = lane & 3;

    float acc[2][8][4];
#pragma unroll
    for (int mi = 0; mi < 2; mi++)
#pragma unroll
        for (int nf = 0; nf < 8; nf++)
#pragma unroll
            for (int e = 0; e < 4; e++) acc[mi][nf][e] = 0.f;

    const uint32_t aA = smem_base;
    const uint32_t aB = smem_base + 3 * PJ_STAGE * 4;

    // prologue: stages 0,1 in flight (k0 = 0, 64)
    pj_issue(aA, aB, abase, bbase, 0, tid);
    pj_issue(aA + PJ_STAGE * 4, aB + PJ_STAGE * 4, abase, bbase, 64, tid);

    for (int it = 0; it < 32; it++) {
        if (it < 31) {
            asm volatile("cp.async.wait_group 1;\n" ::: "memory");
        } else {
            asm volatile("cp.async.wait_group 0;\n" ::: "memory");
        }
        __syncthreads();

        const int st = it % 3;
        const uint32_t* Ac = psm + st * PJ_STAGE;
        const uint32_t* Bc = psm + 3 * PJ_STAGE + st * PJ_STAGE;
#pragma unroll
        for (int ks = 0; ks < 4; ks++) {         // 4 k16 steps = 64 halves
            const int kk = ks * 8;               // word offset
            uint32_t a[2][4];
#pragma unroll
            for (int mi = 0; mi < 2; mi++) {
                int row = wm * 32 + mi * 16 + g;
                a[mi][0] = Ac[row * PJ_STR + kk + qd];
                a[mi][1] = Ac[(row + 8) * PJ_STR + kk + qd];
                a[mi][2] = Ac[row * PJ_STR + kk + qd + 4];
                a[mi][3] = Ac[(row + 8) * PJ_STR + kk + qd + 4];
            }
#pragma unroll
            for (int nf = 0; nf < 8; nf++) {
                int col = wn * 64 + nf * 8 + g;
                uint32_t b0 = Bc[col * PJ_STR + kk + qd];
                uint32_t b1 = Bc[col * PJ_STR + kk + qd + 4];
                mma16(acc[0][nf], a[0], b0, b1);
                mma16(acc[1][nf], a[1], b0, b1);
            }
        }

        if (it + 2 < 32)
            pj_issue(aA + ((it + 2) % 3) * PJ_STAGE * 4,
                     aB + ((it + 2) % 3) * PJ_STAGE * 4,
                     abase, bbase, (it + 2) * 64, tid);
    }

    // Epilogue: RoPE in fp32, write fp16.
    // Q,K -> (b,h,s,dh) half2; V -> transposed (b,h,dh,s) scalar halves.
#pragma unroll
    for (int mi = 0; mi < 2; mi++) {
#pragma unroll
        for (int hh = 0; hh < 2; hh++) {
            int row = m0 + wm * 32 + mi * 16 + g + hh * 8;   // token id
            int b = row >> 11;
            int s = row & (SS - 1);
#pragma unroll
            for (int nf = 0; nf < 8; nf++) {
                int col = n0 + wn * 64 + nf * 8 + qd * 2;    // even
                int h = col >> 7, dh = col & 127;
                float v0 = acc[mi][nf][hh * 2 + 0];
                float v1 = acc[mi][nf][hh * 2 + 1];
                if (z < 2) {
                    float c = rcos[s * DH + dh];
                    float sn = rsin[s * DH + dh];
                    float r0 = v0 * c - v1 * sn;
                    float r1 = v1 * c + v0 * sn;
                    v0 = r0; v1 = r1;
                }
                if (z == 2) {
                    size_t base = (((size_t)b * HH + h) * DH + dh) * SS + s;
                    outp[base] = __float2half_rn(v0);
                    outp[base + SS] = __float2half_rn(v1);
                } else {
                    *(__half2*)(outp + (((size_t)b * HH + h) * SS + s) * DH + dh) =
                        __floats2half2_rn(v0, v1);
                }
            }
        }
    }
}

// ===================== Flash attention + final Dh softmax, fp16 ==============
// 256 threads, q-tile 128, kv-tile 64 (R2-proven shape). All operands fp16,
// softmax + accumulators fp32.  Smem (words): Qs 128x68, Ks 64x68,
// Vs 128x32 (n-major, XOR swizzled), Ps 128x36. Total 87040 B.
#define FQ_STR 68
#define FK_STR 68
#define FP_STR 36
#define OFF_Q 0
#define OFF_K (128 * FQ_STR)                 // 8704
#define OFF_V (OFF_K + 64 * FK_STR)          // 13056
#define OFF_P (OFF_V + 128 * 32)             // 17152
#define FL_SMEM_BYTES ((OFF_P + 128 * FP_STR) * 4)   // 87040

__global__ __launch_bounds__(256, 1) void flash_kernel(float* __restrict__ out)
{
    extern __shared__ uint32_t sm[];
    uint32_t* Qs = sm + OFF_Q;
    uint32_t* Ks = sm + OFF_K;
    uint32_t* Vs = sm + OFF_V;
    uint32_t* Ps = sm + OFF_P;

    const int tid = threadIdx.x, lane = tid & 31, wid = tid >> 5;
    const int bh = blockIdx.y;
    const int qt = gridDim.x - 1 - blockIdx.x;   // big tiles launch first
    const int q0 = qt * 128;
    const int g = lane >> 2, qd = lane & 3;
    const int rw0 = q0 + wid * 16;
    const float e2 = (float)(1.4426950408889634 / 11.313708498984761); // log2(e)/sqrt(128)

    // stage Q tile (128 x 128 halves = 128 x 64 words), raw bit copies
#pragma unroll
    for (int i = 0; i < 8; i++) {
        int idx = tid + 256 * i;
        int r = idx >> 4, c = idx & 15;
        uint4 v = *(const uint4*)(g_q + ((size_t)bh * SS + q0 + r) * DH + c * 8);
        *(uint4*)(Qs + r * FQ_STR + c * 4) = v;
    }

    float oacc[16][4];
#pragma unroll
    for (int nf = 0; nf < 16; nf++)
#pragma unroll
        for (int e = 0; e < 4; e++) oacc[nf][e] = 0.f;
    float m2[2] = {-INFINITY, -INFINITY};
    float lsum[2] = {0.f, 0.f};

    const int ntiles = qt * 2 + 2;
    for (int t = 0; t < ntiles; t++) {
        const int k0g = t * 64;
        __syncthreads();
        // stage K tile (64 x 64 words)
#pragma unroll
        for (int i = 0; i < 4; i++) {
            int idx = tid + 256 * i;
            int r = idx >> 4, c = idx & 15;
            uint4 v = *(const uint4*)(g_k + ((size_t)bh * SS + k0g + r) * DH + c * 8);
            *(uint4*)(Ks + r * FK_STR + c * 4) = v;
        }
        // stage V tile n-major from transposed g_v: Vs[n][kv-word], XOR swizzle
#pragma unroll
        for (int i = 0; i < 4; i++) {
            int idx = tid + 256 * i;
            int n = idx & 127, wg = idx >> 7;     // wg 0..7 -> words wg*4..wg*4+3
            uint4 v = *(const uint4*)(g_v + ((size_t)bh * DH + n) * SS + k0g + wg * 8);
            *(uint4*)(Vs + n * 32 + ((wg ^ (n & 7)) * 4)) = v;
        }
        __syncthreads();

        const bool active = (k0g <= rw0 + 15);
        if (active) {
            float sacc[8][4];
#pragma unroll
            for (int nf = 0; nf < 8; nf++)
#pragma unroll
                for (int e = 0; e < 4; e++) sacc[nf][e] = 0.f;

            // S = Q K^T : Dh=128 halves -> 8 k16 steps
            const int qrow = wid * 16 + g;
#pragma unroll
            for (int kd = 0; kd < 8; kd++) {
                const int kk = kd * 8;
                uint32_t a[4];
                a[0] = Qs[qrow * FQ_STR + kk + qd];
                a[1] = Qs[(qrow + 8) * FQ_STR + kk + qd];
                a[2] = Qs[qrow * FQ_STR + kk + qd + 4];
                a[3] = Qs[(qrow + 8) * FQ_STR + kk + qd + 4];
#pragma unroll
                for (int nf = 0; nf < 8; nf++) {
                    int krow = nf * 8 + g;
                    uint32_t b0 = Ks[krow * FK_STR + kk + qd];
                    uint32_t b1 = Ks[krow * FK_STR + kk + qd + 4];
                    mma16(sacc[nf], a, b0, b1);
                }
            }

            const bool needmask = (k0g + 63 > rw0);
            // online softmax per row-half; scale folded into log2 domain
#pragma unroll
            for (int hh = 0; hh < 2; hh++) {
                int rg = rw0 + g + hh * 8;
                float rmax = -INFINITY;
#pragma unroll
                for (int nf = 0; nf < 8; nf++) {
#pragma unroll
                    for (int e = 0; e < 2; e++) {
                        int col = k0g + nf * 8 + qd * 2 + e;
                        float sv = sacc[nf][hh * 2 + e] * e2;
                        if (needmask && col > rg) sv = -1e30f;
                        sacc[nf][hh * 2 + e] = sv;
                        rmax = fmaxf(rmax, sv);
                    }
                }
                rmax = fmaxf(rmax, __shfl_xor_sync(0xffffffffu, rmax, 1));
                rmax = fmaxf(rmax, __shfl_xor_sync(0xffffffffu, rmax, 2));
                float mnew = fmaxf(m2[hh], rmax);
                float corr = exp2f(m2[hh] - mnew);
                m2[hh] = mnew;
                float psum = 0.f;
                int prow = wid * 16 + g + hh * 8;
#pragma unroll
                for (int nf = 0; nf < 8; nf++) {
                    float p0 = exp2f(sacc[nf][hh * 2 + 0] - mnew);
                    float p1 = exp2f(sacc[nf][hh * 2 + 1] - mnew);
                    psum += p0 + p1;
                    Ps[prow * FP_STR + nf * 4 + qd] = h2u(__floats2half2_rn(p0, p1));
                }
                psum += __shfl_xor_sync(0xffffffffu, psum, 1);
                psum += __shfl_xor_sync(0xffffffffu, psum, 2);
                lsum[hh] = lsum[hh] * corr + psum;
#pragma unroll
                for (int nf = 0; nf < 16; nf++) {
                    oacc[nf][hh * 2 + 0] *= corr;
                    oacc[nf][hh * 2 + 1] *= corr;
                }
            }
            __syncwarp();

            // O += P V : kv=64 halves -> 4 k16 steps, n = Dh=128 -> 16 n-frags
            const int prow = wid * 16 + g;
#pragma unroll
            for (int j = 0; j < 4; j++) {
                uint32_t a[4];
                a[0] = Ps[prow * FP_STR + j * 8 + qd];
                a[1] = Ps[(prow + 8) * FP_STR + j * 8 + qd];
                a[2] = Ps[prow * FP_STR + j * 8 + qd + 4];
                a[3] = Ps[(prow + 8) * FP_STR + j * 8 + qd + 4];
#pragma unroll
                for (int nf = 0; nf < 16; nf++) {
                    int n = nf * 8 + g;
                    uint32_t b0 = Vs[n * 32 + ((j * 8 + qd) ^ ((n & 7) << 2))];
                    uint32_t b1 = Vs[n * 32 + ((j * 8 + qd + 4) ^ ((n & 7) << 2))];
                    mma16(oacc[nf], a, b0, b1);
                }
            }
        }
    }

    // Epilogue: O /= l, then softmax over Dh=128 (quad holds a full row), fp32 out
    const int b = bh >> 4, h = bh & 15;
#pragma unroll
    for (int hh = 0; hh < 2; hh++) {
        int srow = rw0 + g + hh * 8;
        float inv = 1.0f / lsum[hh];
        float vals[32];
        float mx = -INFINITY;
#pragma unroll
        for (int nf = 0; nf < 16; nf++) {
            vals[nf * 2 + 0] = oacc[nf][hh * 2 + 0] * inv;
            vals[nf * 2 + 1] = oacc[nf][hh * 2 + 1] * inv;
            mx = fmaxf(mx, fmaxf(vals[nf * 2], vals[nf * 2 + 1]));
        }
        mx = fmaxf(mx, __shfl_xor_sync(0xffffffffu, mx, 1));
        mx = fmaxf(mx, __shfl_xor_sync(0xffffffffu, mx, 2));
        float ssum = 0.f;
#pragma unroll
        for (int i2 = 0; i2 < 32; i2++) {
            vals[i2] = expf(vals[i2] - mx);
            ssum += vals[i2];
        }
        ssum += __shfl_xor_sync(0xffffffffu, ssum, 1);
        ssum += __shfl_xor_sync(0xffffffffu, ssum, 2);
        float rinv = 1.0f / ssum;
#pragma unroll
        for (int nf = 0; nf < 16; nf++) {
            int col = h * 128 + nf * 8 + qd * 2;
            float2* dst = (float2*)(out + ((size_t)b * SS + srow) * DD + col);
            *dst = make_float2(vals[nf * 2] * rinv, vals[nf * 2 + 1] * rinv);
        }
    }
}

extern "C" void kernel_launch(void* const* d_in, const int* in_sizes, int n_in,
                              void* d_out, int out_size)
{
    const float* x    = (const float*)d_in[0];
    const float* wq   = (const float*)d_in[1];
    const float* wk   = (const float*)d_in[2];
    const float* wv   = (const float*)d_in[3];
    const float* rcos = (const float*)d_in[4];
    const float* rsin = (const float*)d_in[5];
    float* out = (float*)d_out;

    static bool attr_set = false;
    if (!attr_set) {
        cudaFuncSetAttribute(flash_kernel, cudaFuncAttributeMaxDynamicSharedMemorySize, FL_SMEM_BYTES);
        cudaFuncSetAttribute(proj_kernel,  cudaFuncAttributeMaxDynamicSharedMemorySize, PJ_SMEM_BYTES);
        attr_set = true;
    }

    const int nblk = 1184;
    round_kernel<<<nblk, 256>>>(x,  0, (BB * SS * DD) / 8);
    round_kernel<<<nblk, 256>>>(wq, 1, (DD * DD) / 8);
    round_kernel<<<nblk, 256>>>(wk, 2, (DD * DD) / 8);
    round_kernel<<<nblk, 256>>>(wv, 3, (DD * DD) / 8);

    proj_kernel<<<dim3(16, 32, 3), 256, PJ_SMEM_BYTES>>>(rcos, rsin);
    flash_kernel<<<dim3(16, BB * HH), 256, FL_SMEM_BYTES>>>(out);
}